// round 1
// baseline (speedup 1.0000x reference)
#include <cuda_runtime.h>
#include <cstdint>

// DepConv3D: depth-gated 3x3 conv.
// Only weight depth-slices 0 (dn==dc-1) and 1 (dn==dc) ever contribute
// (the reference maps diff>=1 and diff<-1 to the appended zero slice, so
// slice 2 is dead). Decompose into two mask-gated 3x3 convs so the weight
// index is warp-uniform (broadcast LDS) and use packed fma.rn.f32x2 to
// double fp32 FMA throughput (FFMA rt=2/SMSP, f32x2 does 2 lanes/inst).

#define BB 4
#define CC 16
#define HH 512
#define WW 512
#define OCC 32
#define TILE_H 16
#define TILE_W 32
#define FT_H 18
#define FT_W 34
#define FT_WP 35   // odd row stride -> conflict-free stride-2 access across half-warps

__global__ __launch_bounds__(256, 2)
void depconv3d_kernel(const float* __restrict__ feat,
                      const int*   __restrict__ depth,
                      const float* __restrict__ wgt,
                      float* __restrict__ out)
{
    __shared__ float4 sW[9 * 16 * 16];       // [k][i][opair] = {W0[2o],W0[2o+1],W1[2o],W1[2o+1]}  (36 KB)
    __shared__ float  sF[FT_H][FT_WP];       // one input-channel tile
    __shared__ int    sD[FT_H][FT_W];        // depth tile

    const int tx = threadIdx.x;              // 0..15
    const int ty = threadIdx.y;              // 0..15
    const int tid = ty * 16 + tx;
    const int b  = blockIdx.z;
    const int y0 = blockIdx.y * TILE_H;
    const int x0 = blockIdx.x * TILE_W;

    // ---- load + repack weights (broadcast-friendly layout) ----
    for (int idx = tid; idx < 9 * 16 * 16; idx += 256) {
        int op = idx & 15;
        int i  = (idx >> 4) & 15;
        int k  = idx >> 8;
        int o0 = op * 2, o1 = op * 2 + 1;
        float4 v;
        v.x = wgt[((o0 * CC + i) * 3 + 0) * 9 + k];
        v.y = wgt[((o1 * CC + i) * 3 + 0) * 9 + k];
        v.z = wgt[((o0 * CC + i) * 3 + 1) * 9 + k];
        v.w = wgt[((o1 * CC + i) * 3 + 1) * 9 + k];
        sW[idx] = v;
    }

    // ---- load depth tile (zero-padded; padded features are 0 anyway) ----
    for (int idx = tid; idx < FT_H * FT_W; idx += 256) {
        int r = idx / FT_W, c = idx - r * FT_W;
        int gy = y0 + r - 1, gx = x0 + c - 1;
        int d = 0;
        if (gy >= 0 && gy < HH && gx >= 0 && gx < WW)
            d = depth[(b * HH + gy) * WW + gx];
        sD[r][c] = d;
    }
    __syncthreads();

    // ---- per-pixel 9-tap masks (two pixels per thread along x) ----
    const int lx = tx * 2;
    unsigned mA0 = 0, mB0 = 0, mA1 = 0, mB1 = 0;   // A: slice0 (dn==dc-1), B: slice1 (dn==dc)
    {
        int dc0 = sD[ty + 1][lx + 1];
        int dc1 = sD[ty + 1][lx + 2];
        #pragma unroll
        for (int k = 0; k < 9; k++) {
            int ky = k / 3, kx = k - ky * 3;
            int dn0 = sD[ty + ky][lx + kx];
            int dn1 = sD[ty + ky][lx + kx + 1];
            if (dn0 == dc0 - 1) mA0 |= 1u << k;
            if (dn0 == dc0)     mB0 |= 1u << k;
            if (dn1 == dc1 - 1) mA1 |= 1u << k;
            if (dn1 == dc1)     mB1 |= 1u << k;
        }
    }

    unsigned long long acc0[16], acc1[16];
    #pragma unroll
    for (int op = 0; op < 16; op++) { acc0[op] = 0ull; acc1[op] = 0ull; }

    const unsigned swbase = (unsigned)__cvta_generic_to_shared(sW);

    for (int i = 0; i < CC; i++) {
        __syncthreads();
        // stream channel-i feature tile
        const float* fch = feat + ((size_t)(b * CC + i)) * HH * WW;
        for (int idx = tid; idx < FT_H * FT_W; idx += 256) {
            int r = idx / FT_W, c = idx - r * FT_W;
            int gy = y0 + r - 1, gx = x0 + c - 1;
            float v = 0.f;
            if (gy >= 0 && gy < HH && gx >= 0 && gx < WW)
                v = fch[gy * WW + gx];
            sF[r][c] = v;
        }
        __syncthreads();

        #pragma unroll
        for (int k = 0; k < 9; k++) {
            const int ky = k / 3, kx = k - ky * 3;
            float f0 = sF[ty + ky][lx + kx];
            float f1 = sF[ty + ky][lx + kx + 1];
            float a0 = ((mA0 >> k) & 1) ? f0 : 0.f;
            float b0 = ((mB0 >> k) & 1) ? f0 : 0.f;
            float a1 = ((mA1 >> k) & 1) ? f1 : 0.f;
            float b1 = ((mB1 >> k) & 1) ? f1 : 0.f;
            unsigned long long A0, B0, A1, B1;
            asm("mov.b64 %0,{%1,%1};" : "=l"(A0) : "r"(__float_as_uint(a0)));
            asm("mov.b64 %0,{%1,%1};" : "=l"(B0) : "r"(__float_as_uint(b0)));
            asm("mov.b64 %0,{%1,%1};" : "=l"(A1) : "r"(__float_as_uint(a1)));
            asm("mov.b64 %0,{%1,%1};" : "=l"(B1) : "r"(__float_as_uint(b1)));

            const unsigned addr = swbase + (unsigned)((k * 16 + i) * 16) * 16u;
            #pragma unroll
            for (int op = 0; op < 16; op++) {
                unsigned long long w0, w1;
                asm("ld.shared.v2.b64 {%0,%1},[%2];"
                    : "=l"(w0), "=l"(w1) : "r"(addr + op * 16));
                asm("fma.rn.f32x2 %0,%1,%2,%0;" : "+l"(acc0[op]) : "l"(A0), "l"(w0));
                asm("fma.rn.f32x2 %0,%1,%2,%0;" : "+l"(acc0[op]) : "l"(B0), "l"(w1));
                asm("fma.rn.f32x2 %0,%1,%2,%0;" : "+l"(acc1[op]) : "l"(A1), "l"(w0));
                asm("fma.rn.f32x2 %0,%1,%2,%0;" : "+l"(acc1[op]) : "l"(B1), "l"(w1));
            }
        }
    }

    // ---- epilogue: 2 channels x 2 pixels per opair, coalesced STG.64 ----
    const int gx = x0 + lx;
    const int gy = y0 + ty;
    #pragma unroll
    for (int op = 0; op < 16; op++) {
        float2 p0 = *reinterpret_cast<float2*>(&acc0[op]);   // pixel0: (c=2op, c=2op+1)
        float2 p1 = *reinterpret_cast<float2*>(&acc1[op]);   // pixel1
        size_t base = (((size_t)(b * OCC + 2 * op) * HH + gy) * WW) + gx;
        *reinterpret_cast<float2*>(out + base)           = make_float2(p0.x, p1.x);
        *reinterpret_cast<float2*>(out + base + (size_t)HH * WW) = make_float2(p0.y, p1.y);
    }
}

extern "C" void kernel_launch(void* const* d_in, const int* in_sizes, int n_in,
                              void* d_out, int out_size)
{
    const float* feat  = (const float*)d_in[0];
    const int*   depth = (const int*)d_in[1];
    const float* wgt   = (const float*)d_in[2];
    float* out = (float*)d_out;

    dim3 block(16, 16);
    dim3 grid(WW / TILE_W, HH / TILE_H, BB);
    depconv3d_kernel<<<grid, block>>>(feat, depth, wgt, out);
}